// round 15
// baseline (speedup 1.0000x reference)
#include <cuda_runtime.h>
#include <cuda_fp16.h>
#include <mma.h>
#include <math.h>
#include <stdint.h>

using namespace nvcuda;

#define N_TOK 32768
#define NB 64
#define NP 512
#define D 128
#define M 256
#define DV 256
#define EPS_PHI 1e-4f
#define EPS_NORM 1e-8f
#define INV_SQRT_M 0.0625f
#define XSCALE 0.29730177875068026f   // 1/128^0.25
#define KSCALE 256.0f
#define QSCALE 256.0f
#define ESCALE 512.0f
#define C2F (EPS_PHI * INV_SQRT_M * KSCALE)
#define NORM_EPS (EPS_NORM * KSCALE * QSCALE)

#define NTILE 64
#define NTILES (N_TOK / NTILE)

// ---------------- scratch ------------------------------------------------------
__device__ float  g_bmax[NTILES];
__device__ float  g_esum[NTILES * M];
__device__ __align__(16) __half g_Qh[N_TOK * M];
__device__ __align__(16) __half g_Ke[N_TOK * M];

__device__ __forceinline__ void cp16(uint32_t dst, const void* src) {
    asm volatile("cp.async.cg.shared.global [%0], [%1], 16;" :: "r"(dst), "l"(src));
}
__device__ __forceinline__ uint32_t h2bits(__half2 h) { return *(uint32_t*)&h; }

// ---------------- phi: U = X@omega, frag-direct epilogue ---------------------
#define PHI_LDA 136
#define PHI_LDB 264
#define PHI_SMEM 88576

__global__ __launch_bounds__(256, 2) void phi_wmma_kernel(
    const float* __restrict__ Q, const float* __restrict__ K,
    const float* __restrict__ omega) {
    extern __shared__ char smraw[];
    __half* Ahi = (__half*)smraw;
    __half* Bhi = (__half*)(smraw + 17408);
    float*  hsm = (float*)(smraw + 84992);
    float*  mxs = (float*)(smraw + 85248);
    float*  mxs2 = (float*)(smraw + 85504);
    float*  esum2 = (float*)(smraw + 86528);

    const int tid  = threadIdx.x;
    const int warp = tid >> 5, lane = tid & 31;
    const int r4 = lane >> 2, q4 = lane & 3;
    const bool isq = blockIdx.x < NTILES;
    const int tile = isq ? blockIdx.x : blockIdx.x - NTILES;
    const int row0 = tile * NTILE;
    const float* X = isq ? Q : K;

    // ---- load X (scaled) -> Ahi, h per row ----
    {
        int r = tid >> 2, j = tid & 3;
        const float4* src = (const float4*)(X + (size_t)(row0 + r) * D + j * 32);
        __half* ah = Ahi + r * PHI_LDA + j * 32;
        float ss = 0.f;
#pragma unroll
        for (int q = 0; q < 8; q++) {
            float4 v = src[q];
            v.x *= XSCALE; v.y *= XSCALE; v.z *= XSCALE; v.w *= XSCALE;
            ss += v.x * v.x + v.y * v.y + v.z * v.z + v.w * v.w;
            uint2 w = make_uint2(h2bits(__floats2half2_rn(v.x, v.y)),
                                 h2bits(__floats2half2_rn(v.z, v.w)));
            *(uint2*)(ah + q * 4) = w;
        }
        ss += __shfl_xor_sync(0xffffffffu, ss, 1);
        ss += __shfl_xor_sync(0xffffffffu, ss, 2);
        if (j == 0) hsm[r] = 0.5f * ss;
    }
    // ---- convert omega fp32 -> Bhi fp16 (8192 float4 = 32768 floats) ----
#pragma unroll
    for (int it = 0; it < 32; it++) {
        int i = it * 256 + tid;
        int rr = i >> 6, c4 = i & 63;
        float4 v = ((const float4*)omega)[i];
        uint2 w = make_uint2(h2bits(__floats2half2_rn(v.x, v.y)),
                             h2bits(__floats2half2_rn(v.z, v.w)));
        *(uint2*)(Bhi + rr * PHI_LDB + c4 * 4) = w;
    }
    __syncthreads();

    const int wr = warp >> 2, wc = warp & 3;
    wmma::fragment<wmma::accumulator, 16, 16, 16, float> c[2][4];
#pragma unroll
    for (int i = 0; i < 2; i++)
#pragma unroll
        for (int j = 0; j < 4; j++) wmma::fill_fragment(c[i][j], 0.f);

#pragma unroll
    for (int ks = 0; ks < 8; ks++) {
        int kk = ks * 16;
        wmma::fragment<wmma::matrix_a, 16, 16, 16, __half, wmma::row_major> ah[2];
        wmma::fragment<wmma::matrix_b, 16, 16, 16, __half, wmma::row_major> bh[4];
#pragma unroll
        for (int i = 0; i < 2; i++)
            wmma::load_matrix_sync(ah[i], Ahi + (wr * 32 + i * 16) * PHI_LDA + kk, PHI_LDA);
#pragma unroll
        for (int j = 0; j < 4; j++)
            wmma::load_matrix_sync(bh[j], Bhi + kk * PHI_LDB + wc * 64 + j * 16, PHI_LDB);
#pragma unroll
        for (int i = 0; i < 2; i++)
#pragma unroll
            for (int j = 0; j < 4; j++)
                wmma::mma_sync(c[i][j], ah[i], bh[j], c[i][j]);
    }

    if (isq) {
#pragma unroll
        for (int i = 0; i < 2; i++) {
            float mA = -INFINITY, mB = -INFINITY;
#pragma unroll
            for (int j = 0; j < 4; j++) {
                mA = fmaxf(mA, fmaxf(fmaxf(c[i][j].x[0], c[i][j].x[1]),
                                     fmaxf(c[i][j].x[4], c[i][j].x[5])));
                mB = fmaxf(mB, fmaxf(fmaxf(c[i][j].x[2], c[i][j].x[3]),
                                     fmaxf(c[i][j].x[6], c[i][j].x[7])));
            }
            mA = fmaxf(mA, __shfl_xor_sync(0xffffffffu, mA, 1));
            mA = fmaxf(mA, __shfl_xor_sync(0xffffffffu, mA, 2));
            mB = fmaxf(mB, __shfl_xor_sync(0xffffffffu, mB, 1));
            mB = fmaxf(mB, __shfl_xor_sync(0xffffffffu, mB, 2));
            if (q4 == 0) {
                mxs2[(wr * 32 + i * 16 + r4) * 4 + wc]     = mA;
                mxs2[(wr * 32 + i * 16 + r4 + 8) * 4 + wc] = mB;
            }
        }
        __syncthreads();
        if (tid < 64)
            mxs[tid] = fmaxf(fmaxf(mxs2[tid * 4], mxs2[tid * 4 + 1]),
                             fmaxf(mxs2[tid * 4 + 2], mxs2[tid * 4 + 3]));
        __syncthreads();
#pragma unroll
        for (int i = 0; i < 2; i++) {
            int rowA = wr * 32 + i * 16 + r4, rowB = rowA + 8;
            float hmA = hsm[rowA] + mxs[rowA];
            float hmB = hsm[rowB] + mxs[rowB];
            __half2* dA = (__half2*)(g_Qh + (size_t)(row0 + rowA) * M);
            __half2* dB = (__half2*)(g_Qh + (size_t)(row0 + rowB) * M);
#pragma unroll
            for (int j = 0; j < 4; j++) {
                int cb2 = (wc * 64 + j * 16) / 2 + q4;
#pragma unroll
                for (int hf = 0; hf < 2; hf++) {
                    int kb = hf * 4;
                    float a0 = (__expf(c[i][j].x[kb + 0] - hmA) + EPS_PHI) * (INV_SQRT_M * QSCALE);
                    float a1 = (__expf(c[i][j].x[kb + 1] - hmA) + EPS_PHI) * (INV_SQRT_M * QSCALE);
                    float b0 = (__expf(c[i][j].x[kb + 2] - hmB) + EPS_PHI) * (INV_SQRT_M * QSCALE);
                    float b1 = (__expf(c[i][j].x[kb + 3] - hmB) + EPS_PHI) * (INV_SQRT_M * QSCALE);
                    dA[cb2 + hf * 4] = __floats2half2_rn(a0, a1);
                    dB[cb2 + hf * 4] = __floats2half2_rn(b0, b1);
                }
            }
        }
    } else {
        float bm = -INFINITY;
#pragma unroll
        for (int i = 0; i < 2; i++)
#pragma unroll
            for (int j = 0; j < 4; j++)
#pragma unroll
                for (int e = 0; e < 8; e++) bm = fmaxf(bm, c[i][j].x[e]);
#pragma unroll
        for (int o = 16; o > 0; o >>= 1) bm = fmaxf(bm, __shfl_xor_sync(0xffffffffu, bm, o));
        if (lane == 0) mxs[warp] = bm;
        __syncthreads();
        float bmax = mxs[0];
#pragma unroll
        for (int w = 1; w < 8; w++) bmax = fmaxf(bmax, mxs[w]);

        float es[16];
#pragma unroll
        for (int t = 0; t < 16; t++) es[t] = 0.f;
#pragma unroll
        for (int i = 0; i < 2; i++) {
            int rowA = wr * 32 + i * 16 + r4, rowB = rowA + 8;
            float hmA = hsm[rowA] + bmax;
            float hmB = hsm[rowB] + bmax;
            __half2* dA = (__half2*)(g_Ke + (size_t)(row0 + rowA) * M);
            __half2* dB = (__half2*)(g_Ke + (size_t)(row0 + rowB) * M);
#pragma unroll
            for (int j = 0; j < 4; j++) {
                int cb2 = (wc * 64 + j * 16) / 2 + q4;
#pragma unroll
                for (int hf = 0; hf < 2; hf++) {
                    int kb = hf * 4;
                    float a0 = __expf(c[i][j].x[kb + 0] - hmA) * ESCALE;
                    float a1 = __expf(c[i][j].x[kb + 1] - hmA) * ESCALE;
                    float b0 = __expf(c[i][j].x[kb + 2] - hmB) * ESCALE;
                    float b1 = __expf(c[i][j].x[kb + 3] - hmB) * ESCALE;
                    dA[cb2 + hf * 4] = __floats2half2_rn(a0, a1);
                    dB[cb2 + hf * 4] = __floats2half2_rn(b0, b1);
                    es[j * 4 + hf * 2 + 0] += a0 + b0;
                    es[j * 4 + hf * 2 + 1] += a1 + b1;
                }
            }
        }
#pragma unroll
        for (int t = 0; t < 16; t++) {
            es[t] += __shfl_xor_sync(0xffffffffu, es[t], 4);
            es[t] += __shfl_xor_sync(0xffffffffu, es[t], 8);
            es[t] += __shfl_xor_sync(0xffffffffu, es[t], 16);
        }
        if (lane < 4) {
#pragma unroll
            for (int j = 0; j < 4; j++)
#pragma unroll
                for (int hf = 0; hf < 2; hf++)
#pragma unroll
                    for (int p = 0; p < 2; p++) {
                        int col = wc * 64 + j * 16 + lane * 2 + p + 8 * hf;
                        esum2[wr * 256 + col] = es[j * 4 + hf * 2 + p];
                    }
        }
        __syncthreads();
        g_esum[tile * M + tid] = esum2[tid] + esum2[256 + tid];
        if (tid == 0) g_bmax[tile] = bmax;
    }
}

// ---------------- fused segment kernel ---------------------------------------
// KVs: [256][152] halves. Cols 0-127 KV, 128 Ksum_hi, 129 Ksum_lo, 130 ones,
// 131-143 zero. Norm via MMA, k-split between vc==2 (k<128) and vc==3 (k>=128).
#define LDA 264
#define LDB 136
#define LDB2 152
#define ST_OFF  77824
#define ST_SZ   51200
#define AS2_OFF 77824
#define AS2_SZ  67584
#define VSUM_OFF 214016
#define NPP_OFF 214528   // float[2][128]
#define QSP_OFF 215552   // float[2][128]
#define SMEMF   216576

__global__ __launch_bounds__(512, 1) void fused_kernel(const float* __restrict__ V,
                                                       float* __restrict__ out) {
    extern __shared__ char smraw[];
    __half* KVs  = (__half*)smraw;
    float*  vsum = (float*)(smraw + VSUM_OFF);
    float*  npp  = (float*)(smraw + NPP_OFF);
    float*  qsp  = (float*)(smraw + QSP_OFF);
    const uint32_t sbase = (uint32_t)__cvta_generic_to_shared(smraw);

    const int tid = threadIdx.x, warp = tid >> 5, lane = tid & 31;
    const int r4 = lane >> 2, q4 = lane & 3;
    const int vh = blockIdx.x, b = blockIdx.y;

    const __half* Ke = g_Ke + (size_t)b * NP * M;
    const float*  Vb = V    + (size_t)b * NP * DV + vh * 128;

    // --- lambdas for phase-1 copies ---
    auto copyA = [&](int s, int ch) {
        uint32_t abase = sbase + ST_OFF + s * ST_SZ;
        const __half* src = Ke + (size_t)(ch * 64) * M;
#pragma unroll
        for (int u = 0; u < 4; u++) {
            int i = tid + u * 512, t = i >> 5, q = i & 31;
            cp16(abase + (t * LDA + q * 8) * 2, src + (size_t)t * M + q * 8);
        }
        asm volatile("cp.async.commit_group;");
    };
    float4 Breg[4], Breg2[4];
    auto loadB = [&](float4* rg, int ch) {
        const float* src = Vb + (size_t)(ch * 64) * DV;
#pragma unroll
        for (int u = 0; u < 4; u++) {
            int i = tid + u * 512, t = i >> 5, q = i & 31;
            rg[u] = ((const float4*)(src + (size_t)t * DV))[q];
        }
    };

    // issue first loads immediately; setup math overlaps them
    copyA(0, 0);
    loadB(Breg, 0);

    float bm8[8];
#pragma unroll
    for (int cb = 0; cb < 8; cb++) bm8[cb] = g_bmax[b * 8 + cb];
    float sgm = bm8[0];
#pragma unroll
    for (int cb = 1; cb < 8; cb++) sgm = fmaxf(sgm, bm8[cb]);

    if (tid < M) {
        float s = 0.f;
#pragma unroll
        for (int cb = 0; cb < 8; cb++)
            s += __expf(bm8[cb] - sgm) * g_esum[(b * 8 + cb) * M + tid];
        float val = (s * (1.f / ESCALE) + NP * EPS_PHI) * (INV_SQRT_M * KSCALE);
        __half hhi = __float2half_rn(val);
        __half* kr = KVs + tid * LDB2;
        kr[128] = hhi;
        kr[129] = __float2half_rn(val - __half2float(hhi));
        kr[130] = __float2half_rn(1.0f);
#pragma unroll
        for (int z = 131; z < 144; z++) kr[z] = __float2half_rn(0.f);
    }
    if (tid < 128) vsum[tid] = 0.f;

    float corrf[8];
#pragma unroll
    for (int cb = 0; cb < 8; cb++)
        corrf[cb] = __expf(bm8[cb] - sgm) * (INV_SQRT_M * KSCALE / ESCALE);

    // ================= PHASE 1: KV-half into KVs =================
    const int wr1 = warp & 7, wv = warp >> 3;

    float4 vpart = make_float4(0.f, 0.f, 0.f, 0.f);
    auto storeB = [&](const float4* rg, int s, float cf) {
        __half* Bs = (__half*)(smraw + ST_OFF + s * ST_SZ + 33792);
#pragma unroll
        for (int u = 0; u < 4; u++) {
            int i = tid + u * 512, t = i >> 5, q = i & 31;
            float4 f = rg[u];
            vpart.x += f.x; vpart.y += f.y; vpart.z += f.z; vpart.w += f.w;
            uint2 w = make_uint2(h2bits(__floats2half2_rn(f.x * cf, f.y * cf)),
                                 h2bits(__floats2half2_rn(f.z * cf, f.w * cf)));
            *(uint2*)(Bs + t * LDB + q * 4) = w;
        }
    };

    wmma::fragment<wmma::accumulator, 16, 16, 16, float> c1[2][4];
#pragma unroll
    for (int i = 0; i < 2; i++)
#pragma unroll
        for (int j = 0; j < 4; j++) wmma::fill_fragment(c1[i][j], 0.f);

    for (int ch = 0; ch < 8; ch++) {
        int s = ch & 1;
        if (ch < 7) copyA(s ^ 1, ch + 1);
        if (ch < 7) asm volatile("cp.async.wait_group 1;");
        else        asm volatile("cp.async.wait_group 0;");
        storeB(Breg, s, corrf[ch]);
        __syncthreads();
        if (ch < 7) loadB(Breg2, ch + 1);

        const __half* As = (const __half*)(smraw + ST_OFF + s * ST_SZ);
        const __half* Bs = As + 33792 / 2;
#pragma unroll
        for (int kk = 0; kk < 64; kk += 16) {
            wmma::fragment<wmma::matrix_a, 16, 16, 16, __half, wmma::col_major> a[2];
#pragma unroll
            for (int i = 0; i < 2; i++)
                wmma::load_matrix_sync(a[i], As + kk * LDA + wr1 * 32 + i * 16, LDA);
#pragma unroll
            for (int j = 0; j < 4; j++) {
                wmma::fragment<wmma::matrix_b, 16, 16, 16, __half, wmma::row_major> bf;
                wmma::load_matrix_sync(bf, Bs + kk * LDB + wv * 64 + j * 16, LDB);
#pragma unroll
                for (int i = 0; i < 2; i++)
                    wmma::mma_sync(c1[i][j], a[i], bf, c1[i][j]);
            }
        }
        __syncthreads();
#pragma unroll
        for (int u = 0; u < 4; u++) Breg[u] = Breg2[u];
    }

    // phase-2 chunk-0 A prefetch
    {
        uint32_t abase = sbase + AS2_OFF;
        const __half* src = g_Qh + (size_t)b * NP * M;
#pragma unroll
        for (int u = 0; u < 8; u++) {
            int i = tid + u * 512, t = i >> 5, q = i & 31;
            cp16(abase + (t * LDA + q * 8) * 2, src + (size_t)t * M + q * 8);
        }
        asm volatile("cp.async.commit_group;");
    }

    {
        int q = tid & 31;
        atomicAdd(&vsum[q * 4 + 0], vpart.x);
        atomicAdd(&vsum[q * 4 + 1], vpart.y);
        atomicAdd(&vsum[q * 4 + 2], vpart.z);
        atomicAdd(&vsum[q * 4 + 3], vpart.w);
    }
#pragma unroll
    for (int i = 0; i < 2; i++)
#pragma unroll
        for (int j = 0; j < 4; j++) {
            wmma::fragment<wmma::accumulator, 16, 16, 16, __half> hf;
#pragma unroll
            for (int e = 0; e < hf.num_elements; e++)
                hf.x[e] = __float2half_rn(c1[i][j].x[e]);
            wmma::store_matrix_sync(KVs + (wr1 * 32 + i * 16) * LDB2 + wv * 64 + j * 16,
                                    hf, LDB2, wmma::mem_row_major);
        }

    // ================= PHASE 2: 4 chunks of 128 tokens =================
    const int tr = warp >> 2, vc = warp & 3;
    const __half* Qh = g_Qh + (size_t)b * NP * M;

    for (int c = 0; c < 4; c++) {
        int s = c & 1;
        asm volatile("cp.async.wait_group 0;");
        __syncthreads();

        if (c < 3) {
            uint32_t abase = sbase + AS2_OFF + (s ^ 1) * AS2_SZ;
            const __half* src = Qh + (size_t)((c + 1) * 128) * M;
#pragma unroll
            for (int u = 0; u < 8; u++) {
                int i = tid + u * 512, t = i >> 5, q = i & 31;
                cp16(abase + (t * LDA + q * 8) * 2, src + (size_t)t * M + q * 8);
            }
            asm volatile("cp.async.commit_group;");
        }

        const __half* As2 = (const __half*)(smraw + AS2_OFF + s * AS2_SZ);

        wmma::fragment<wmma::accumulator, 16, 16, 16, float> c2[2][2];
        wmma::fragment<wmma::accumulator, 16, 16, 16, float> cn[2];
#pragma unroll
        for (int i = 0; i < 2; i++) {
#pragma unroll
            for (int j = 0; j < 2; j++) wmma::fill_fragment(c2[i][j], 0.f);
            wmma::fill_fragment(cn[i], 0.f);
        }

#pragma unroll
        for (int ks = 0; ks < 16; ks++) {
            int kk = ks * 16;
            wmma::fragment<wmma::matrix_a, 16, 16, 16, __half, wmma::row_major> a[2];
            wmma::fragment<wmma::matrix_b, 16, 16, 16, __half, wmma::row_major> bf[2];
#pragma unroll
            for (int i = 0; i < 2; i++)
                wmma::load_matrix_sync(a[i], As2 + (tr * 32 + i * 16) * LDA + kk, LDA);
#pragma unroll
            for (int j = 0; j < 2; j++)
                wmma::load_matrix_sync(bf[j], KVs + kk * LDB2 + vc * 32 + j * 16, LDB2);
#pragma unroll
            for (int i = 0; i < 2; i++)
#pragma unroll
                for (int j = 0; j < 2; j++)
                    wmma::mma_sync(c2[i][j], a[i], bf[j], c2[i][j]);
            // norm columns: k-halves split between vc==2 and vc==3
            if (vc == (ks < 8 ? 2 : 3)) {
                wmma::fragment<wmma::matrix_b, 16, 16, 16, __half, wmma::row_major> bn;
                wmma::load_matrix_sync(bn, KVs + kk * LDB2 + 128, LDB2);
#pragma unroll
                for (int i = 0; i < 2; i++)
                    wmma::mma_sync(cn[i], a[i], bn, cn[i]);
            }
        }

        if (vc >= 2) {
            int h = (vc - 2) * 128;
#pragma unroll
            for (int i = 0; i < 2; i++) {
                int rowA = tr * 32 + i * 16 + r4, rowB = rowA + 8;
                if (q4 == 0) {
                    npp[h + rowA] = cn[i].x[0] + cn[i].x[1];
                    npp[h + rowB] = cn[i].x[2] + cn[i].x[3];
                } else if (q4 == 1) {
                    qsp[h + rowA] = cn[i].x[0];
                    qsp[h + rowB] = cn[i].x[2];
                }
            }
        }
        __syncthreads();

        // epilogue: fp32 rank-1 + inv scaling, direct gmem store
        float* op = out + ((size_t)(b * NP + c * 128 + tr * 32)) * DV + vh * 128 + vc * 32;
#pragma unroll
        for (int i = 0; i < 2; i++) {
            int rb = tr * 32 + i * 16;
            int rA = rb + r4, rB = rb + r4 + 8;
            float invA = 1.0f / (npp[rA] + npp[128 + rA] + NORM_EPS);
            float invB = 1.0f / (npp[rB] + npp[128 + rB] + NORM_EPS);
            float q1A = (qsp[rA] + qsp[128 + rA]) * C2F;
            float q1B = (qsp[rB] + qsp[128 + rB]) * C2F;
#pragma unroll
            for (int j = 0; j < 2; j++) {
                int cb = vc * 32 + j * 16 + q4 * 2;
                float vs0 = vsum[cb], vs1 = vsum[cb + 1];
                float vs8 = vsum[cb + 8], vs9 = vsum[cb + 9];
                c2[i][j].x[0] = (c2[i][j].x[0] + q1A * vs0) * invA;
                c2[i][j].x[1] = (c2[i][j].x[1] + q1A * vs1) * invA;
                c2[i][j].x[2] = (c2[i][j].x[2] + q1B * vs0) * invB;
                c2[i][j].x[3] = (c2[i][j].x[3] + q1B * vs1) * invB;
                c2[i][j].x[4] = (c2[i][j].x[4] + q1A * vs8) * invA;
                c2[i][j].x[5] = (c2[i][j].x[5] + q1A * vs9) * invA;
                c2[i][j].x[6] = (c2[i][j].x[6] + q1B * vs8) * invB;
                c2[i][j].x[7] = (c2[i][j].x[7] + q1B * vs9) * invB;
                wmma::store_matrix_sync(op + (size_t)(i * 16) * DV + j * 16,
                                        c2[i][j], DV, wmma::mem_row_major);
            }
        }
    }
}

// ---------------- launch ------------------------------------------------------
extern "C" void kernel_launch(void* const* d_in, const int* in_sizes, int n_in,
                              void* d_out, int out_size) {
    const float* Q     = (const float*)d_in[0];
    const float* K     = (const float*)d_in[1];
    const float* V     = (const float*)d_in[2];
    const float* omega = (const float*)d_in[3];
    float* out = (float*)d_out;

    cudaFuncSetAttribute(phi_wmma_kernel, cudaFuncAttributeMaxDynamicSharedMemorySize, PHI_SMEM);
    cudaFuncSetAttribute(fused_kernel,    cudaFuncAttributeMaxDynamicSharedMemorySize, SMEMF);

    phi_wmma_kernel<<<2 * NTILES, 256, PHI_SMEM>>>(Q, K, omega);
    fused_kernel<<<dim3(2, NB), 512, SMEMF>>>(V, out);
}

// round 16
// speedup vs baseline: 1.0011x; 1.0011x over previous
#include <cuda_runtime.h>
#include <cuda_fp16.h>
#include <mma.h>
#include <math.h>
#include <stdint.h>

using namespace nvcuda;

#define N_TOK 32768
#define NB 64
#define NP 512
#define D 128
#define M 256
#define DV 256
#define EPS_PHI 1e-4f
#define EPS_NORM 1e-8f
#define INV_SQRT_M 0.0625f
#define XSCALE 0.29730177875068026f   // 1/128^0.25
#define KSCALE 256.0f
#define QSCALE 256.0f
#define ESCALE 512.0f
#define C2F (EPS_PHI * INV_SQRT_M * KSCALE)
#define NORM_EPS (EPS_NORM * KSCALE * QSCALE)

#define NTILE 64
#define NTILES (N_TOK / NTILE)

// ---------------- scratch ------------------------------------------------------
__device__ float  g_bmax[NTILES];
__device__ float  g_esum[NTILES * M];
__device__ __align__(16) __half g_Qh[N_TOK * M];
__device__ __align__(16) __half g_Ke[N_TOK * M];
__device__ __align__(16) __half g_Whi[D * M];

__device__ __forceinline__ void cp16(uint32_t dst, const void* src) {
    asm volatile("cp.async.cg.shared.global [%0], [%1], 16;" :: "r"(dst), "l"(src));
}
__device__ __forceinline__ uint32_t h2bits(__half2 h) { return *(uint32_t*)&h; }

__global__ void omega_split_kernel(const float* __restrict__ omega) {
    int i = blockIdx.x * 256 + threadIdx.x;
    g_Whi[i] = __float2half_rn(omega[i]);
}

// ---------------- phi: U = X@omega, frag-direct epilogue (R14 version) -------
#define PHI_LDA 136
#define PHI_LDB 264
#define PHI_SMEM 88576

__global__ __launch_bounds__(256, 2) void phi_wmma_kernel(
    const float* __restrict__ Q, const float* __restrict__ K) {
    extern __shared__ char smraw[];
    __half* Ahi = (__half*)smraw;
    __half* Bhi = (__half*)(smraw + 17408);
    float*  hsm = (float*)(smraw + 84992);
    float*  mxs = (float*)(smraw + 85248);
    float*  mxs2 = (float*)(smraw + 85504);
    float*  esum2 = (float*)(smraw + 86528);
    const uint32_t sbase = (uint32_t)__cvta_generic_to_shared(smraw);

    const int tid  = threadIdx.x;
    const int warp = tid >> 5, lane = tid & 31;
    const int r4 = lane >> 2, q4 = lane & 3;
    const bool isq = blockIdx.x < NTILES;
    const int tile = isq ? blockIdx.x : blockIdx.x - NTILES;
    const int row0 = tile * NTILE;
    const float* X = isq ? Q : K;

#pragma unroll
    for (int u = 0; u < 16; u++) {
        int i = u * 256 + tid;
        int r = i >> 5, q = i & 31;
        cp16(sbase + 17408 + r * (PHI_LDB * 2) + q * 16, g_Whi + r * 256 + q * 8);
    }
    asm volatile("cp.async.commit_group;");

    {
        int r = tid >> 2, j = tid & 3;
        const float4* src = (const float4*)(X + (size_t)(row0 + r) * D + j * 32);
        __half* ah = Ahi + r * PHI_LDA + j * 32;
        float ss = 0.f;
#pragma unroll
        for (int q = 0; q < 8; q++) {
            float4 v = src[q];
            v.x *= XSCALE; v.y *= XSCALE; v.z *= XSCALE; v.w *= XSCALE;
            ss += v.x * v.x + v.y * v.y + v.z * v.z + v.w * v.w;
            uint2 w = make_uint2(h2bits(__floats2half2_rn(v.x, v.y)),
                                 h2bits(__floats2half2_rn(v.z, v.w)));
            *(uint2*)(ah + q * 4) = w;
        }
        ss += __shfl_xor_sync(0xffffffffu, ss, 1);
        ss += __shfl_xor_sync(0xffffffffu, ss, 2);
        if (j == 0) hsm[r] = 0.5f * ss;
    }
    asm volatile("cp.async.wait_group 0;");
    __syncthreads();

    const int wr = warp >> 2, wc = warp & 3;
    wmma::fragment<wmma::accumulator, 16, 16, 16, float> c[2][4];
#pragma unroll
    for (int i = 0; i < 2; i++)
#pragma unroll
        for (int j = 0; j < 4; j++) wmma::fill_fragment(c[i][j], 0.f);

#pragma unroll
    for (int ks = 0; ks < 8; ks++) {
        int kk = ks * 16;
        wmma::fragment<wmma::matrix_a, 16, 16, 16, __half, wmma::row_major> ah[2];
        wmma::fragment<wmma::matrix_b, 16, 16, 16, __half, wmma::row_major> bh[4];
#pragma unroll
        for (int i = 0; i < 2; i++)
            wmma::load_matrix_sync(ah[i], Ahi + (wr * 32 + i * 16) * PHI_LDA + kk, PHI_LDA);
#pragma unroll
        for (int j = 0; j < 4; j++)
            wmma::load_matrix_sync(bh[j], Bhi + kk * PHI_LDB + wc * 64 + j * 16, PHI_LDB);
#pragma unroll
        for (int i = 0; i < 2; i++)
#pragma unroll
            for (int j = 0; j < 4; j++)
                wmma::mma_sync(c[i][j], ah[i], bh[j], c[i][j]);
    }

    if (isq) {
#pragma unroll
        for (int i = 0; i < 2; i++) {
            float mA = -INFINITY, mB = -INFINITY;
#pragma unroll
            for (int j = 0; j < 4; j++) {
                mA = fmaxf(mA, fmaxf(fmaxf(c[i][j].x[0], c[i][j].x[1]),
                                     fmaxf(c[i][j].x[4], c[i][j].x[5])));
                mB = fmaxf(mB, fmaxf(fmaxf(c[i][j].x[2], c[i][j].x[3]),
                                     fmaxf(c[i][j].x[6], c[i][j].x[7])));
            }
            mA = fmaxf(mA, __shfl_xor_sync(0xffffffffu, mA, 1));
            mA = fmaxf(mA, __shfl_xor_sync(0xffffffffu, mA, 2));
            mB = fmaxf(mB, __shfl_xor_sync(0xffffffffu, mB, 1));
            mB = fmaxf(mB, __shfl_xor_sync(0xffffffffu, mB, 2));
            if (q4 == 0) {
                mxs2[(wr * 32 + i * 16 + r4) * 4 + wc]     = mA;
                mxs2[(wr * 32 + i * 16 + r4 + 8) * 4 + wc] = mB;
            }
        }
        __syncthreads();
        if (tid < 64)
            mxs[tid] = fmaxf(fmaxf(mxs2[tid * 4], mxs2[tid * 4 + 1]),
                             fmaxf(mxs2[tid * 4 + 2], mxs2[tid * 4 + 3]));
        __syncthreads();
#pragma unroll
        for (int i = 0; i < 2; i++) {
            int rowA = wr * 32 + i * 16 + r4, rowB = rowA + 8;
            float hmA = hsm[rowA] + mxs[rowA];
            float hmB = hsm[rowB] + mxs[rowB];
            __half2* dA = (__half2*)(g_Qh + (size_t)(row0 + rowA) * M);
            __half2* dB = (__half2*)(g_Qh + (size_t)(row0 + rowB) * M);
#pragma unroll
            for (int j = 0; j < 4; j++) {
                int cb2 = (wc * 64 + j * 16) / 2 + q4;
#pragma unroll
                for (int hf = 0; hf < 2; hf++) {
                    int kb = hf * 4;
                    float a0 = (__expf(c[i][j].x[kb + 0] - hmA) + EPS_PHI) * (INV_SQRT_M * QSCALE);
                    float a1 = (__expf(c[i][j].x[kb + 1] - hmA) + EPS_PHI) * (INV_SQRT_M * QSCALE);
                    float b0 = (__expf(c[i][j].x[kb + 2] - hmB) + EPS_PHI) * (INV_SQRT_M * QSCALE);
                    float b1 = (__expf(c[i][j].x[kb + 3] - hmB) + EPS_PHI) * (INV_SQRT_M * QSCALE);
                    dA[cb2 + hf * 4] = __floats2half2_rn(a0, a1);
                    dB[cb2 + hf * 4] = __floats2half2_rn(b0, b1);
                }
            }
        }
    } else {
        float bm = -INFINITY;
#pragma unroll
        for (int i = 0; i < 2; i++)
#pragma unroll
            for (int j = 0; j < 4; j++)
#pragma unroll
                for (int e = 0; e < 8; e++) bm = fmaxf(bm, c[i][j].x[e]);
#pragma unroll
        for (int o = 16; o > 0; o >>= 1) bm = fmaxf(bm, __shfl_xor_sync(0xffffffffu, bm, o));
        if (lane == 0) mxs[warp] = bm;
        __syncthreads();
        float bmax = mxs[0];
#pragma unroll
        for (int w = 1; w < 8; w++) bmax = fmaxf(bmax, mxs[w]);

        float es[16];
#pragma unroll
        for (int t = 0; t < 16; t++) es[t] = 0.f;
#pragma unroll
        for (int i = 0; i < 2; i++) {
            int rowA = wr * 32 + i * 16 + r4, rowB = rowA + 8;
            float hmA = hsm[rowA] + bmax;
            float hmB = hsm[rowB] + bmax;
            __half2* dA = (__half2*)(g_Ke + (size_t)(row0 + rowA) * M);
            __half2* dB = (__half2*)(g_Ke + (size_t)(row0 + rowB) * M);
#pragma unroll
            for (int j = 0; j < 4; j++) {
                int cb2 = (wc * 64 + j * 16) / 2 + q4;
#pragma unroll
                for (int hf = 0; hf < 2; hf++) {
                    int kb = hf * 4;
                    float a0 = __expf(c[i][j].x[kb + 0] - hmA) * ESCALE;
                    float a1 = __expf(c[i][j].x[kb + 1] - hmA) * ESCALE;
                    float b0 = __expf(c[i][j].x[kb + 2] - hmB) * ESCALE;
                    float b1 = __expf(c[i][j].x[kb + 3] - hmB) * ESCALE;
                    dA[cb2 + hf * 4] = __floats2half2_rn(a0, a1);
                    dB[cb2 + hf * 4] = __floats2half2_rn(b0, b1);
                    es[j * 4 + hf * 2 + 0] += a0 + b0;
                    es[j * 4 + hf * 2 + 1] += a1 + b1;
                }
            }
        }
#pragma unroll
        for (int t = 0; t < 16; t++) {
            es[t] += __shfl_xor_sync(0xffffffffu, es[t], 4);
            es[t] += __shfl_xor_sync(0xffffffffu, es[t], 8);
            es[t] += __shfl_xor_sync(0xffffffffu, es[t], 16);
        }
        if (lane < 4) {
#pragma unroll
            for (int j = 0; j < 4; j++)
#pragma unroll
                for (int hf = 0; hf < 2; hf++)
#pragma unroll
                    for (int p = 0; p < 2; p++) {
                        int col = wc * 64 + j * 16 + lane * 2 + p + 8 * hf;
                        esum2[wr * 256 + col] = es[j * 4 + hf * 2 + p];
                    }
        }
        __syncthreads();
        g_esum[tile * M + tid] = esum2[tid] + esum2[256 + tid];
        if (tid == 0) g_bmax[tile] = bmax;
    }
}

// ---------------- fused segment kernel: v-QUARTER blocks, 2/SM ----------------
// KVs [256][88]: cols 0-63 KV quarter, 64 Ksum_hi, 65 Ksum_lo, 66 ones, 67-87 pad0
#define LDA 264
#define LDB1 72
#define LDB2 88
#define KVS_SZ  45056
#define ST_OFF  45056
#define ST_STAGE 21504      // A 16896 + B 4608
#define AS2_OFF 45056       // [128][264] halves = 67584
#define VSUM_OFF 112640     // 64 f
#define NPP_OFF 112896      // [2][128] f
#define QSP_OFF 113920      // [2][128] f
#define SMEMF   114944

__global__ __launch_bounds__(256, 2) void fused_kernel(const float* __restrict__ V,
                                                       float* __restrict__ out) {
    extern __shared__ char smraw[];
    __half* KVs  = (__half*)smraw;
    float*  vsum = (float*)(smraw + VSUM_OFF);
    float*  npp  = (float*)(smraw + NPP_OFF);
    float*  qsp  = (float*)(smraw + QSP_OFF);
    const uint32_t sbase = (uint32_t)__cvta_generic_to_shared(smraw);

    const int tid = threadIdx.x, warp = tid >> 5, lane = tid & 31;
    const int r4 = lane >> 2, q4 = lane & 3;
    const int vq = blockIdx.x, b = blockIdx.y;

    const __half* Ke = g_Ke + (size_t)b * NP * M;
    const float*  Vb = V    + (size_t)b * NP * DV + vq * 64;

    auto copyA = [&](int s, int ch) {     // 32 tokens x 256 m
        uint32_t abase = sbase + ST_OFF + s * ST_STAGE;
        const __half* src = Ke + (size_t)(ch * 32) * M;
#pragma unroll
        for (int u = 0; u < 4; u++) {
            int i = tid + u * 256, t = i >> 5, q = i & 31;
            cp16(abase + (t * LDA + q * 8) * 2, src + (size_t)t * M + q * 8);
        }
        asm volatile("cp.async.commit_group;");
    };
    float4 Breg[2], Breg2[2];
    auto loadB = [&](float4* rg, int ch) {   // 32 tokens x 64 v (quarter)
        const float* src = Vb + (size_t)(ch * 32) * DV;
#pragma unroll
        for (int u = 0; u < 2; u++) {
            int i = tid + u * 256, t = i >> 4, q = i & 15;
            rg[u] = ((const float4*)(src + (size_t)t * DV))[q];
        }
    };

    copyA(0, 0);
    loadB(Breg, 0);

    // setup overlaps first loads
    float bm8[8];
#pragma unroll
    for (int cb = 0; cb < 8; cb++) bm8[cb] = g_bmax[b * 8 + cb];
    float sgm = bm8[0];
#pragma unroll
    for (int cb = 1; cb < 8; cb++) sgm = fmaxf(sgm, bm8[cb]);

    {   // Ksum aug cols (tid = m row, 256 threads)
        float s = 0.f;
#pragma unroll
        for (int cb = 0; cb < 8; cb++)
            s += __expf(bm8[cb] - sgm) * g_esum[(b * 8 + cb) * M + tid];
        float val = (s * (1.f / ESCALE) + NP * EPS_PHI) * (INV_SQRT_M * KSCALE);
        __half hhi = __float2half_rn(val);
        __half* kr = KVs + tid * LDB2;
        kr[64] = hhi;
        kr[65] = __float2half_rn(val - __half2float(hhi));
        kr[66] = __float2half_rn(1.0f);
#pragma unroll
        for (int z = 67; z < 80; z++) kr[z] = __float2half_rn(0.f);
    }
    if (tid < 64) vsum[tid] = 0.f;

    float corrf[8];
#pragma unroll
    for (int cb = 0; cb < 8; cb++)
        corrf[cb] = __expf(bm8[cb] - sgm) * (INV_SQRT_M * KSCALE / ESCALE);

    // ================= PHASE 1: 16 chunks of 32 tokens =================
    float4 vpart = make_float4(0.f, 0.f, 0.f, 0.f);
    auto storeB = [&](const float4* rg, int s, float cf) {
        __half* Bs = (__half*)(smraw + ST_OFF + s * ST_STAGE + 16896);
#pragma unroll
        for (int u = 0; u < 2; u++) {
            int i = tid + u * 256, t = i >> 4, q = i & 15;
            float4 f = rg[u];
            vpart.x += f.x; vpart.y += f.y; vpart.z += f.z; vpart.w += f.w;
            uint2 w = make_uint2(h2bits(__floats2half2_rn(f.x * cf, f.y * cf)),
                                 h2bits(__floats2half2_rn(f.z * cf, f.w * cf)));
            *(uint2*)(Bs + t * LDB1 + q * 4) = w;
        }
    };

    wmma::fragment<wmma::accumulator, 16, 16, 16, float> c1[2][4];
#pragma unroll
    for (int i = 0; i < 2; i++)
#pragma unroll
        for (int j = 0; j < 4; j++) wmma::fill_fragment(c1[i][j], 0.f);

    const int wr1 = warp;   // 8 warps: 32 m each, full 64 v
    for (int ch = 0; ch < 16; ch++) {
        int s = ch & 1;
        if (ch < 15) copyA(s ^ 1, ch + 1);
        if (ch < 15) asm volatile("cp.async.wait_group 1;");
        else         asm volatile("cp.async.wait_group 0;");
        storeB(Breg, s, corrf[ch >> 1]);
        __syncthreads();
        if (ch < 15) loadB(Breg2, ch + 1);

        const __half* As = (const __half*)(smraw + ST_OFF + s * ST_STAGE);
        const __half* Bs = As + 16896 / 2;
#pragma unroll
        for (int kk = 0; kk < 32; kk += 16) {
            wmma::fragment<wmma::matrix_a, 16, 16, 16, __half, wmma::col_major> a[2];
#pragma unroll
            for (int i = 0; i < 2; i++)
                wmma::load_matrix_sync(a[i], As + kk * LDA + wr1 * 32 + i * 16, LDA);
#pragma unroll
            for (int j = 0; j < 4; j++) {
                wmma::fragment<wmma::matrix_b, 16, 16, 16, __half, wmma::row_major> bf;
                wmma::load_matrix_sync(bf, Bs + kk * LDB1 + j * 16, LDB1);
#pragma unroll
                for (int i = 0; i < 2; i++)
                    wmma::mma_sync(c1[i][j], a[i], bf, c1[i][j]);
            }
        }
        __syncthreads();
        Breg[0] = Breg2[0]; Breg[1] = Breg2[1];
    }

    // phase-2 chunk-0 prefetch (ST region free after last barrier)
    {
        uint32_t abase = sbase + AS2_OFF;
        const __half* src = g_Qh + (size_t)b * NP * M;
#pragma unroll
        for (int u = 0; u < 16; u++) {
            int i = tid + u * 256, t = i >> 5, q = i & 31;
            cp16(abase + (t * LDA + q * 8) * 2, src + (size_t)t * M + q * 8);
        }
        asm volatile("cp.async.commit_group;");
    }

    {
        int q = tid & 15;
        atomicAdd(&vsum[q * 4 + 0], vpart.x);
        atomicAdd(&vsum[q * 4 + 1], vpart.y);
        atomicAdd(&vsum[q * 4 + 2], vpart.z);
        atomicAdd(&vsum[q * 4 + 3], vpart.w);
    }
#pragma unroll
    for (int i = 0; i < 2; i++)
#pragma unroll
        for (int j = 0; j < 4; j++) {
            wmma::fragment<wmma::accumulator, 16, 16, 16, __half> hf;
#pragma unroll
            for (int e = 0; e < hf.num_elements; e++)
                hf.x[e] = __float2half_rn(c1[i][j].x[e]);
            wmma::store_matrix_sync(KVs + (wr1 * 32 + i * 16) * LDB2 + j * 16,
                                    hf, LDB2, wmma::mem_row_major);
        }
    __syncthreads();   // KVs + vsum visible

    // ================= PHASE 2: 4 chunks of 128 tokens =================
    const int tr = warp >> 1, vc = warp & 1;    // 4 t-tiles x 2 v-tiles of 32x32
    const __half* Qh = g_Qh + (size_t)b * NP * M;

    for (int c = 0; c < 4; c++) {
        asm volatile("cp.async.wait_group 0;");
        __syncthreads();   // As2 ready across threads

        const __half* As2 = (const __half*)(smraw + AS2_OFF);

        wmma::fragment<wmma::accumulator, 16, 16, 16, float> c2[2][2];
        wmma::fragment<wmma::accumulator, 16, 16, 16, float> cn[2];
#pragma unroll
        for (int i = 0; i < 2; i++) {
#pragma unroll
            for (int j = 0; j < 2; j++) wmma::fill_fragment(c2[i][j], 0.f);
            wmma::fill_fragment(cn[i], 0.f);
        }

#pragma unroll
        for (int ks = 0; ks < 16; ks++) {
            int kk = ks * 16;
            wmma::fragment<wmma::matrix_a, 16, 16, 16, __half, wmma::row_major> a[2];
            wmma::fragment<wmma::matrix_b, 16, 16, 16, __half, wmma::row_major> bf[2];
#pragma unroll
            for (int i = 0; i < 2; i++)
                wmma::load_matrix_sync(a[i], As2 + (tr * 32 + i * 16) * LDA + kk, LDA);
#pragma unroll
            for (int j = 0; j < 2; j++)
                wmma::load_matrix_sync(bf[j], KVs + kk * LDB2 + vc * 32 + j * 16, LDB2);
#pragma unroll
            for (int i = 0; i < 2; i++)
#pragma unroll
                for (int j = 0; j < 2; j++)
                    wmma::mma_sync(c2[i][j], a[i], bf[j], c2[i][j]);
            if (vc == (ks < 8 ? 0 : 1)) {      // norm cols 64-79, k-split
                wmma::fragment<wmma::matrix_b, 16, 16, 16, __half, wmma::row_major> bn;
                wmma::load_matrix_sync(bn, KVs + kk * LDB2 + 64, LDB2);
#pragma unroll
                for (int i = 0; i < 2; i++)
                    wmma::mma_sync(cn[i], a[i], bn, cn[i]);
            }
        }

        {   // norm partials (half per vc)
            int h = vc * 128;
#pragma unroll
            for (int i = 0; i < 2; i++) {
                int rowA = tr * 32 + i * 16 + r4, rowB = rowA + 8;
                if (q4 == 0) {
                    npp[h + rowA] = cn[i].x[0] + cn[i].x[1];
                    npp[h + rowB] = cn[i].x[2] + cn[i].x[3];
                } else if (q4 == 1) {
                    qsp[h + rowA] = cn[i].x[0];
                    qsp[h + rowB] = cn[i].x[2];
                }
            }
        }
        __syncthreads();   // npp/qsp visible; all MMA reads of As2 done

        if (c < 3) {       // prefetch next chunk, flies under epilogue
            uint32_t abase = sbase + AS2_OFF;
            const __half* src = Qh + (size_t)((c + 1) * 128) * M;
#pragma unroll
            for (int u = 0; u < 16; u++) {
                int i = tid + u * 256, t = i >> 5, q = i & 31;
                cp16(abase + (t * LDA + q * 8) * 2, src + (size_t)t * M + q * 8);
            }
            asm volatile("cp.async.commit_group;");
        }

        // epilogue: fp32 rank-1 + inv scaling, direct gmem store
        float* op = out + ((size_t)(b * NP + c * 128 + tr * 32)) * DV + vq * 64 + vc * 32;
#pragma unroll
        for (int i = 0; i < 2; i++) {
            int rb = tr * 32 + i * 16;
            int rA = rb + r4, rB = rb + r4 + 8;
            float invA = 1.0f / (npp[rA] + npp[128 + rA] + NORM_EPS);
            float invB = 1.0f / (npp[rB] + npp[128 + rB] + NORM_EPS);
            float q1A = (qsp[rA] + qsp[128 + rA]) * C2F;
            float q1B = (qsp[rB] + qsp[128 + rB]) * C2F;
#pragma unroll
            for (int j = 0; j < 2; j++) {
                int cb = vc * 32 + j * 16 + q4 * 2;
                float vs0 = vsum[cb], vs1 = vsum[cb + 1];
                float vs8 = vsum[cb + 8], vs9 = vsum[cb + 9];
                c2[i][j].x[0] = (c2[i][j].x[0] + q1A * vs0) * invA;
                c2[i][j].x[1] = (c2[i][j].x[1] + q1A * vs1) * invA;
                c2[i][j].x[2] = (c2[i][j].x[2] + q1B * vs0) * invB;
                c2[i][j].x[3] = (c2[i][j].x[3] + q1B * vs1) * invB;
                c2[i][j].x[4] = (c2[i][j].x[4] + q1A * vs8) * invA;
                c2[i][j].x[5] = (c2[i][j].x[5] + q1A * vs9) * invA;
                c2[i][j].x[6] = (c2[i][j].x[6] + q1B * vs8) * invB;
                c2[i][j].x[7] = (c2[i][j].x[7] + q1B * vs9) * invB;
                wmma::store_matrix_sync(op + (size_t)(i * 16) * DV + j * 16,
                                        c2[i][j], DV, wmma::mem_row_major);
            }
        }
    }
}

// ---------------- launch ------------------------------------------------------
extern "C" void kernel_launch(void* const* d_in, const int* in_sizes, int n_in,
                              void* d_out, int out_size) {
    const float* Q     = (const float*)d_in[0];
    const float* K     = (const float*)d_in[1];
    const float* V     = (const float*)d_in[2];
    const float* omega = (const float*)d_in[3];
    float* out = (float*)d_out;

    cudaFuncSetAttribute(phi_wmma_kernel, cudaFuncAttributeMaxDynamicSharedMemorySize, PHI_SMEM);
    cudaFuncSetAttribute(fused_kernel,    cudaFuncAttributeMaxDynamicSharedMemorySize, SMEMF);

    omega_split_kernel<<<(D * M) / 256, 256>>>(omega);
    phi_wmma_kernel<<<2 * NTILES, 256, PHI_SMEM>>>(Q, K);
    fused_kernel<<<dim3(4, NB), 256, SMEMF>>>(V, out);
}

// round 17
// speedup vs baseline: 1.0040x; 1.0029x over previous
#include <cuda_runtime.h>
#include <cuda_fp16.h>
#include <mma.h>
#include <math.h>
#include <stdint.h>

using namespace nvcuda;

#define N_TOK 32768
#define NB 64
#define NP 512
#define D 128
#define M 256
#define DV 256
#define EPS_PHI 1e-4f
#define EPS_NORM 1e-8f
#define INV_SQRT_M 0.0625f
#define XSCALE 0.29730177875068026f   // 1/128^0.25
#define KSCALE 256.0f
#define QSCALE 256.0f
#define ESCALE 512.0f
#define C2F (EPS_PHI * INV_SQRT_M * KSCALE)
#define NORM_EPS (EPS_NORM * KSCALE * QSCALE)

#define NTILE 64
#define NTILES (N_TOK / NTILE)

// ---------------- scratch ------------------------------------------------------
__device__ float  g_bmax[NTILES];
__device__ float  g_esum[NTILES * M];
__device__ __align__(16) __half g_Qh[N_TOK * M];
__device__ __align__(16) __half g_Ke[N_TOK * M];

__device__ __forceinline__ void cp16(uint32_t dst, const void* src) {
    asm volatile("cp.async.cg.shared.global [%0], [%1], 16;" :: "r"(dst), "l"(src));
}
__device__ __forceinline__ uint32_t h2bits(__half2 h) { return *(uint32_t*)&h; }

// ---------------- phi: paired Q+K tiles per block ----------------------------
// 256 threads, 2 blocks/SM. One block: omega once, then Q-tile and K-tile.
#define PHI_LDA 136
#define PHI_LDB 264
#define PHI_SMEM 88576

__global__ __launch_bounds__(256, 2) void phi_pair_kernel(
    const float* __restrict__ Q, const float* __restrict__ K,
    const float* __restrict__ omega) {
    extern __shared__ char smraw[];
    __half* Ahi = (__half*)smraw;
    __half* Bhi = (__half*)(smraw + 17408);
    float*  hsm = (float*)(smraw + 84992);
    float*  mxs = (float*)(smraw + 85248);
    float*  mxs2 = (float*)(smraw + 85504);
    float*  esum2 = (float*)(smraw + 86528);

    const int tid  = threadIdx.x;
    const int warp = tid >> 5, lane = tid & 31;
    const int r4 = lane >> 2, q4 = lane & 3;
    const int tile = blockIdx.x;
    const int row0 = tile * NTILE;
    const int wr = warp >> 2, wc = warp & 3;

    // ---- convert omega fp32 -> Bhi fp16 ONCE (8192 float4) ----
#pragma unroll
    for (int it = 0; it < 32; it++) {
        int i = it * 256 + tid;
        int rr = i >> 6, c4 = i & 63;
        float4 v = ((const float4*)omega)[i];
        uint2 w = make_uint2(h2bits(__floats2half2_rn(v.x, v.y)),
                             h2bits(__floats2half2_rn(v.z, v.w)));
        *(uint2*)(Bhi + rr * PHI_LDB + c4 * 4) = w;
    }

#pragma unroll
    for (int ph = 0; ph < 2; ph++) {
        if (ph == 1) __syncthreads();   // protect hsm/Ahi from phase-0 readers
        const float* X = (ph == 0) ? Q : K;

        // ---- load X (scaled) -> Ahi, h per row ----
        {
            int r = tid >> 2, j = tid & 3;
            const float4* src = (const float4*)(X + (size_t)(row0 + r) * D + j * 32);
            __half* ah = Ahi + r * PHI_LDA + j * 32;
            float ss = 0.f;
#pragma unroll
            for (int q = 0; q < 8; q++) {
                float4 v = src[q];
                v.x *= XSCALE; v.y *= XSCALE; v.z *= XSCALE; v.w *= XSCALE;
                ss += v.x * v.x + v.y * v.y + v.z * v.z + v.w * v.w;
                uint2 w = make_uint2(h2bits(__floats2half2_rn(v.x, v.y)),
                                     h2bits(__floats2half2_rn(v.z, v.w)));
                *(uint2*)(ah + q * 4) = w;
            }
            ss += __shfl_xor_sync(0xffffffffu, ss, 1);
            ss += __shfl_xor_sync(0xffffffffu, ss, 2);
            if (j == 0) hsm[r] = 0.5f * ss;
        }
        __syncthreads();

        wmma::fragment<wmma::accumulator, 16, 16, 16, float> c[2][4];
#pragma unroll
        for (int i = 0; i < 2; i++)
#pragma unroll
            for (int j = 0; j < 4; j++) wmma::fill_fragment(c[i][j], 0.f);

#pragma unroll
        for (int ks = 0; ks < 8; ks++) {
            int kk = ks * 16;
            wmma::fragment<wmma::matrix_a, 16, 16, 16, __half, wmma::row_major> ah[2];
            wmma::fragment<wmma::matrix_b, 16, 16, 16, __half, wmma::row_major> bh[4];
#pragma unroll
            for (int i = 0; i < 2; i++)
                wmma::load_matrix_sync(ah[i], Ahi + (wr * 32 + i * 16) * PHI_LDA + kk, PHI_LDA);
#pragma unroll
            for (int j = 0; j < 4; j++)
                wmma::load_matrix_sync(bh[j], Bhi + kk * PHI_LDB + wc * 64 + j * 16, PHI_LDB);
#pragma unroll
            for (int i = 0; i < 2; i++)
#pragma unroll
                for (int j = 0; j < 4; j++)
                    wmma::mma_sync(c[i][j], ah[i], bh[j], c[i][j]);
        }

        if (ph == 0) {
            // ---- Q epilogue: per-row max, exp, direct gmem fp16 store ----
#pragma unroll
            for (int i = 0; i < 2; i++) {
                float mA = -INFINITY, mB = -INFINITY;
#pragma unroll
                for (int j = 0; j < 4; j++) {
                    mA = fmaxf(mA, fmaxf(fmaxf(c[i][j].x[0], c[i][j].x[1]),
                                         fmaxf(c[i][j].x[4], c[i][j].x[5])));
                    mB = fmaxf(mB, fmaxf(fmaxf(c[i][j].x[2], c[i][j].x[3]),
                                         fmaxf(c[i][j].x[6], c[i][j].x[7])));
                }
                mA = fmaxf(mA, __shfl_xor_sync(0xffffffffu, mA, 1));
                mA = fmaxf(mA, __shfl_xor_sync(0xffffffffu, mA, 2));
                mB = fmaxf(mB, __shfl_xor_sync(0xffffffffu, mB, 1));
                mB = fmaxf(mB, __shfl_xor_sync(0xffffffffu, mB, 2));
                if (q4 == 0) {
                    mxs2[(wr * 32 + i * 16 + r4) * 4 + wc]     = mA;
                    mxs2[(wr * 32 + i * 16 + r4 + 8) * 4 + wc] = mB;
                }
            }
            __syncthreads();
            if (tid < 64)
                mxs[tid] = fmaxf(fmaxf(mxs2[tid * 4], mxs2[tid * 4 + 1]),
                                 fmaxf(mxs2[tid * 4 + 2], mxs2[tid * 4 + 3]));
            __syncthreads();
#pragma unroll
            for (int i = 0; i < 2; i++) {
                int rowA = wr * 32 + i * 16 + r4, rowB = rowA + 8;
                float hmA = hsm[rowA] + mxs[rowA];
                float hmB = hsm[rowB] + mxs[rowB];
                __half2* dA = (__half2*)(g_Qh + (size_t)(row0 + rowA) * M);
                __half2* dB = (__half2*)(g_Qh + (size_t)(row0 + rowB) * M);
#pragma unroll
                for (int j = 0; j < 4; j++) {
                    int cb2 = (wc * 64 + j * 16) / 2 + q4;
#pragma unroll
                    for (int hf = 0; hf < 2; hf++) {
                        int kb = hf * 4;
                        float a0 = (__expf(c[i][j].x[kb + 0] - hmA) + EPS_PHI) * (INV_SQRT_M * QSCALE);
                        float a1 = (__expf(c[i][j].x[kb + 1] - hmA) + EPS_PHI) * (INV_SQRT_M * QSCALE);
                        float b0 = (__expf(c[i][j].x[kb + 2] - hmB) + EPS_PHI) * (INV_SQRT_M * QSCALE);
                        float b1 = (__expf(c[i][j].x[kb + 3] - hmB) + EPS_PHI) * (INV_SQRT_M * QSCALE);
                        dA[cb2 + hf * 4] = __floats2half2_rn(a0, a1);
                        dB[cb2 + hf * 4] = __floats2half2_rn(b0, b1);
                    }
                }
            }
        } else {
            // ---- K epilogue: block max, exp*ESCALE store, column sums ----
            float bm = -INFINITY;
#pragma unroll
            for (int i = 0; i < 2; i++)
#pragma unroll
                for (int j = 0; j < 4; j++)
#pragma unroll
                    for (int e = 0; e < 8; e++) bm = fmaxf(bm, c[i][j].x[e]);
#pragma unroll
            for (int o = 16; o > 0; o >>= 1) bm = fmaxf(bm, __shfl_xor_sync(0xffffffffu, bm, o));
            if (lane == 0) mxs[warp] = bm;
            __syncthreads();
            float bmax = mxs[0];
#pragma unroll
            for (int w = 1; w < 8; w++) bmax = fmaxf(bmax, mxs[w]);

            float es[16];
#pragma unroll
            for (int t = 0; t < 16; t++) es[t] = 0.f;
#pragma unroll
            for (int i = 0; i < 2; i++) {
                int rowA = wr * 32 + i * 16 + r4, rowB = rowA + 8;
                float hmA = hsm[rowA] + bmax;
                float hmB = hsm[rowB] + bmax;
                __half2* dA = (__half2*)(g_Ke + (size_t)(row0 + rowA) * M);
                __half2* dB = (__half2*)(g_Ke + (size_t)(row0 + rowB) * M);
#pragma unroll
                for (int j = 0; j < 4; j++) {
                    int cb2 = (wc * 64 + j * 16) / 2 + q4;
#pragma unroll
                    for (int hf = 0; hf < 2; hf++) {
                        int kb = hf * 4;
                        float a0 = __expf(c[i][j].x[kb + 0] - hmA) * ESCALE;
                        float a1 = __expf(c[i][j].x[kb + 1] - hmA) * ESCALE;
                        float b0 = __expf(c[i][j].x[kb + 2] - hmB) * ESCALE;
                        float b1 = __expf(c[i][j].x[kb + 3] - hmB) * ESCALE;
                        dA[cb2 + hf * 4] = __floats2half2_rn(a0, a1);
                        dB[cb2 + hf * 4] = __floats2half2_rn(b0, b1);
                        es[j * 4 + hf * 2 + 0] += a0 + b0;
                        es[j * 4 + hf * 2 + 1] += a1 + b1;
                    }
                }
            }
#pragma unroll
            for (int t = 0; t < 16; t++) {
                es[t] += __shfl_xor_sync(0xffffffffu, es[t], 4);
                es[t] += __shfl_xor_sync(0xffffffffu, es[t], 8);
                es[t] += __shfl_xor_sync(0xffffffffu, es[t], 16);
            }
            if (lane < 4) {
#pragma unroll
                for (int j = 0; j < 4; j++)
#pragma unroll
                    for (int hf = 0; hf < 2; hf++)
#pragma unroll
                        for (int p = 0; p < 2; p++) {
                            int col = wc * 64 + j * 16 + lane * 2 + p + 8 * hf;
                            esum2[wr * 256 + col] = es[j * 4 + hf * 2 + p];
                        }
            }
            __syncthreads();
            g_esum[tile * M + tid] = esum2[tid] + esum2[256 + tid];
            if (tid == 0) g_bmax[tile] = bmax;
        }
    }
}

// ---------------- fused segment kernel (R14 winner, verbatim) ----------------
// KVs: [256][152] halves. Cols 0-127 KV, 128 Ksum_hi, 129 Ksum_lo, 130 ones,
// 131-143 zero. Norm computed as extra MMA columns by vc==3 warps.
#define LDA 264
#define LDB 136
#define LDB2 152
#define ST_OFF  77824
#define ST_SZ   51200
#define AS2_OFF 77824
#define AS2_SZ  67584
#define VSUM_OFF 214016
#define INV_OFF 214528
#define Q1_OFF  215040
#define SMEMF   215552

__global__ __launch_bounds__(512, 1) void fused_kernel(const float* __restrict__ V,
                                                       float* __restrict__ out) {
    extern __shared__ char smraw[];
    __half* KVs  = (__half*)smraw;
    float*  vsum = (float*)(smraw + VSUM_OFF);
    float*  invbuf = (float*)(smraw + INV_OFF);
    float*  q1buf  = (float*)(smraw + Q1_OFF);
    const uint32_t sbase = (uint32_t)__cvta_generic_to_shared(smraw);

    const int tid = threadIdx.x, warp = tid >> 5, lane = tid & 31;
    const int r4 = lane >> 2, q4 = lane & 3;
    const int vh = blockIdx.x, b = blockIdx.y;

    float bm8[8];
#pragma unroll
    for (int cb = 0; cb < 8; cb++) bm8[cb] = g_bmax[b * 8 + cb];
    float sgm = bm8[0];
#pragma unroll
    for (int cb = 1; cb < 8; cb++) sgm = fmaxf(sgm, bm8[cb]);

    if (tid < M) {
        float s = 0.f;
#pragma unroll
        for (int cb = 0; cb < 8; cb++)
            s += __expf(bm8[cb] - sgm) * g_esum[(b * 8 + cb) * M + tid];
        float val = (s * (1.f / ESCALE) + NP * EPS_PHI) * (INV_SQRT_M * KSCALE);
        __half hhi = __float2half_rn(val);
        __half* kr = KVs + tid * LDB2;
        kr[128] = hhi;
        kr[129] = __float2half_rn(val - __half2float(hhi));
        kr[130] = __float2half_rn(1.0f);
#pragma unroll
        for (int z = 131; z < 144; z++) kr[z] = __float2half_rn(0.f);
    }
    if (tid < 128) vsum[tid] = 0.f;

    float corrf[8];
#pragma unroll
    for (int cb = 0; cb < 8; cb++)
        corrf[cb] = __expf(bm8[cb] - sgm) * (INV_SQRT_M * KSCALE / ESCALE);

    const __half* Ke = g_Ke + (size_t)b * NP * M;
    const float*  Vb = V    + (size_t)b * NP * DV + vh * 128;

    // ================= PHASE 1: KV-half into KVs =================
    const int wr1 = warp & 7, wv = warp >> 3;

    auto copyA = [&](int s, int ch) {
        uint32_t abase = sbase + ST_OFF + s * ST_SZ;
        const __half* src = Ke + (size_t)(ch * 64) * M;
#pragma unroll
        for (int u = 0; u < 4; u++) {
            int i = tid + u * 512, t = i >> 5, q = i & 31;
            cp16(abase + (t * LDA + q * 8) * 2, src + (size_t)t * M + q * 8);
        }
        asm volatile("cp.async.commit_group;");
    };

    float4 Breg[4], Breg2[4];
    auto loadB = [&](float4* rg, int ch) {
        const float* src = Vb + (size_t)(ch * 64) * DV;
#pragma unroll
        for (int u = 0; u < 4; u++) {
            int i = tid + u * 512, t = i >> 5, q = i & 31;
            rg[u] = ((const float4*)(src + (size_t)t * DV))[q];
        }
    };
    float4 vpart = make_float4(0.f, 0.f, 0.f, 0.f);
    auto storeB = [&](const float4* rg, int s, float cf) {
        __half* Bs = (__half*)(smraw + ST_OFF + s * ST_SZ + 33792);
#pragma unroll
        for (int u = 0; u < 4; u++) {
            int i = tid + u * 512, t = i >> 5, q = i & 31;
            float4 f = rg[u];
            vpart.x += f.x; vpart.y += f.y; vpart.z += f.z; vpart.w += f.w;
            uint2 w = make_uint2(h2bits(__floats2half2_rn(f.x * cf, f.y * cf)),
                                 h2bits(__floats2half2_rn(f.z * cf, f.w * cf)));
            *(uint2*)(Bs + t * LDB + q * 4) = w;
        }
    };

    wmma::fragment<wmma::accumulator, 16, 16, 16, float> c1[2][4];
#pragma unroll
    for (int i = 0; i < 2; i++)
#pragma unroll
        for (int j = 0; j < 4; j++) wmma::fill_fragment(c1[i][j], 0.f);

    copyA(0, 0);
    loadB(Breg, 0);

    for (int ch = 0; ch < 8; ch++) {
        int s = ch & 1;
        if (ch < 7) copyA(s ^ 1, ch + 1);
        if (ch < 7) asm volatile("cp.async.wait_group 1;");
        else        asm volatile("cp.async.wait_group 0;");
        storeB(Breg, s, corrf[ch]);
        __syncthreads();
        if (ch < 7) loadB(Breg2, ch + 1);

        const __half* As = (const __half*)(smraw + ST_OFF + s * ST_SZ);
        const __half* Bs = As + 33792 / 2;
#pragma unroll
        for (int kk = 0; kk < 64; kk += 16) {
            wmma::fragment<wmma::matrix_a, 16, 16, 16, __half, wmma::col_major> a[2];
#pragma unroll
            for (int i = 0; i < 2; i++)
                wmma::load_matrix_sync(a[i], As + kk * LDA + wr1 * 32 + i * 16, LDA);
#pragma unroll
            for (int j = 0; j < 4; j++) {
                wmma::fragment<wmma::matrix_b, 16, 16, 16, __half, wmma::row_major> bf;
                wmma::load_matrix_sync(bf, Bs + kk * LDB + wv * 64 + j * 16, LDB);
#pragma unroll
                for (int i = 0; i < 2; i++)
                    wmma::mma_sync(c1[i][j], a[i], bf, c1[i][j]);
            }
        }
        __syncthreads();
#pragma unroll
        for (int u = 0; u < 4; u++) Breg[u] = Breg2[u];
    }

    // phase-2 chunk-0 A prefetch
    {
        uint32_t abase = sbase + AS2_OFF;
        const __half* src = g_Qh + (size_t)b * NP * M;
#pragma unroll
        for (int u = 0; u < 8; u++) {
            int i = tid + u * 512, t = i >> 5, q = i & 31;
            cp16(abase + (t * LDA + q * 8) * 2, src + (size_t)t * M + q * 8);
        }
        asm volatile("cp.async.commit_group;");
    }

    {
        int q = tid & 31;
        atomicAdd(&vsum[q * 4 + 0], vpart.x);
        atomicAdd(&vsum[q * 4 + 1], vpart.y);
        atomicAdd(&vsum[q * 4 + 2], vpart.z);
        atomicAdd(&vsum[q * 4 + 3], vpart.w);
    }
#pragma unroll
    for (int i = 0; i < 2; i++)
#pragma unroll
        for (int j = 0; j < 4; j++) {
            wmma::fragment<wmma::accumulator, 16, 16, 16, __half> hf;
#pragma unroll
            for (int e = 0; e < hf.num_elements; e++)
                hf.x[e] = __float2half_rn(c1[i][j].x[e]);
            wmma::store_matrix_sync(KVs + (wr1 * 32 + i * 16) * LDB2 + wv * 64 + j * 16,
                                    hf, LDB2, wmma::mem_row_major);
        }

    // ================= PHASE 2: 4 chunks of 128 tokens =================
    const int tr = warp >> 2, vc = warp & 3;
    const __half* Qh = g_Qh + (size_t)b * NP * M;

    for (int c = 0; c < 4; c++) {
        int s = c & 1;
        asm volatile("cp.async.wait_group 0;");
        __syncthreads();

        if (c < 3) {
            uint32_t abase = sbase + AS2_OFF + (s ^ 1) * AS2_SZ;
            const __half* src = Qh + (size_t)((c + 1) * 128) * M;
#pragma unroll
            for (int u = 0; u < 8; u++) {
                int i = tid + u * 512, t = i >> 5, q = i & 31;
                cp16(abase + (t * LDA + q * 8) * 2, src + (size_t)t * M + q * 8);
            }
            asm volatile("cp.async.commit_group;");
        }

        const __half* As2 = (const __half*)(smraw + AS2_OFF + s * AS2_SZ);

        wmma::fragment<wmma::accumulator, 16, 16, 16, float> c2[2][2];
        wmma::fragment<wmma::accumulator, 16, 16, 16, float> cn[2];
#pragma unroll
        for (int i = 0; i < 2; i++) {
#pragma unroll
            for (int j = 0; j < 2; j++) wmma::fill_fragment(c2[i][j], 0.f);
            wmma::fill_fragment(cn[i], 0.f);
        }

#pragma unroll
        for (int ks = 0; ks < 16; ks++) {
            int kk = ks * 16;
            wmma::fragment<wmma::matrix_a, 16, 16, 16, __half, wmma::row_major> a[2];
            wmma::fragment<wmma::matrix_b, 16, 16, 16, __half, wmma::row_major> bf[2];
#pragma unroll
            for (int i = 0; i < 2; i++)
                wmma::load_matrix_sync(a[i], As2 + (tr * 32 + i * 16) * LDA + kk, LDA);
#pragma unroll
            for (int j = 0; j < 2; j++)
                wmma::load_matrix_sync(bf[j], KVs + kk * LDB2 + vc * 32 + j * 16, LDB2);
#pragma unroll
            for (int i = 0; i < 2; i++)
#pragma unroll
                for (int j = 0; j < 2; j++)
                    wmma::mma_sync(c2[i][j], a[i], bf[j], c2[i][j]);
            if (vc == 3) {     // norm columns 128-143
                wmma::fragment<wmma::matrix_b, 16, 16, 16, __half, wmma::row_major> bn;
                wmma::load_matrix_sync(bn, KVs + kk * LDB2 + 128, LDB2);
#pragma unroll
                for (int i = 0; i < 2; i++)
                    wmma::mma_sync(cn[i], a[i], bn, cn[i]);
            }
        }

        if (vc == 3) {
#pragma unroll
            for (int i = 0; i < 2; i++) {
                int rowA = tr * 32 + i * 16 + r4, rowB = rowA + 8;
                if (q4 == 0) {
                    invbuf[rowA] = 1.0f / (cn[i].x[0] + cn[i].x[1] + NORM_EPS);
                    invbuf[rowB] = 1.0f / (cn[i].x[2] + cn[i].x[3] + NORM_EPS);
                } else if (q4 == 1) {
                    q1buf[rowA] = cn[i].x[0] * C2F;
                    q1buf[rowB] = cn[i].x[2] * C2F;
                }
            }
        }
        __syncthreads();

        float* op = out + ((size_t)(b * NP + c * 128 + tr * 32)) * DV + vh * 128 + vc * 32;
#pragma unroll
        for (int i = 0; i < 2; i++) {
            int rb = tr * 32 + i * 16;
            float invA = invbuf[rb + r4],     q1A = q1buf[rb + r4];
            float invB = invbuf[rb + r4 + 8], q1B = q1buf[rb + r4 + 8];
#pragma unroll
            for (int j = 0; j < 2; j++) {
                int cb = vc * 32 + j * 16 + q4 * 2;
                float vs0 = vsum[cb], vs1 = vsum[cb + 1];
                float vs8 = vsum[cb + 8], vs9 = vsum[cb + 9];
                c2[i][j].x[0] = (c2[i][j].x[0] + q1A * vs0) * invA;
                c2[i][j].x[1] = (c2[i][j].x[1] + q1A * vs1) * invA;
                c2[i][j].x[2] = (c2[i][j].x[2] + q1B * vs0) * invB;
                c2[i][j].x[3] = (c2[i][j].x[3] + q1B * vs1) * invB;
                c2[i][j].x[4] = (c2[i][j].x[4] + q1A * vs8) * invA;
                c2[i][j].x[5] = (c2[i][j].x[5] + q1A * vs9) * invA;
                c2[i][j].x[6] = (c2[i][j].x[6] + q1B * vs8) * invB;
                c2[i][j].x[7] = (c2[i][j].x[7] + q1B * vs9) * invB;
                wmma::store_matrix_sync(op + (size_t)(i * 16) * DV + j * 16,
                                        c2[i][j], DV, wmma::mem_row_major);
            }
        }
    }
}

// ---------------- launch ------------------------------------------------------
extern "C" void kernel_launch(void* const* d_in, const int* in_sizes, int n_in,
                              void* d_out, int out_size) {
    const float* Q     = (const float*)d_in[0];
    const float* K     = (const float*)d_in[1];
    const float* V     = (const float*)d_in[2];
    const float* omega = (const float*)d_in[3];
    float* out = (float*)d_out;

    cudaFuncSetAttribute(phi_pair_kernel, cudaFuncAttributeMaxDynamicSharedMemorySize, PHI_SMEM);
    cudaFuncSetAttribute(fused_kernel,    cudaFuncAttributeMaxDynamicSharedMemorySize, SMEMF);

    phi_pair_kernel<<<NTILES, 256, PHI_SMEM>>>(Q, K, omega);
    fused_kernel<<<dim3(2, NB), 512, SMEMF>>>(V, out);
}